// round 4
// baseline (speedup 1.0000x reference)
#include <cuda_runtime.h>
#include <math.h>

// ---------------- problem dims ----------------
#define SS    128
#define BB    64
#define EE    512
#define HH    256
#define DHH   512
#define G4H   1024
#define GD    2048
#define LDWD  2052
#define LMAXX 4
#define CC    9

#define NBE   128     // encoder persistent blocks
#define NBD   128     // decoder persistent blocks

// gate-interleaved permutations: n' -> original row n
// encoder (4H=1024 rows): n = q*256 + ni*16 + jj  where ni=n'>>6, q=(n'>>4)&3, jj=n'&15
__device__ __forceinline__ int enperm(int np) { return (((np >> 4) & 3) << 8) + ((np >> 6) << 4) + (np & 15); }
// decoder (4DH=2048 rows): n = q*512 + ni*16 + jj
__device__ __forceinline__ int deperm(int np) { return (((np >> 4) & 3) << 9) + ((np >> 6) << 4) + (np & 15); }

// ---------------- static device scratch ----------------
__device__ float g_x   [SS*BB*EE];
__device__ float g_gxf [SS*BB*G4H];      // permuted n'
__device__ float g_gxb [SS*BB*G4H];      // permuted n'
__device__ float g_h   [SS*BB*DHH];
__device__ float g_wh  [SS*BB*DHH];
__device__ float g_preS[SS*BB*GD];       // permuted n'
__device__ float g_pre0[SS*BB*GD];       // permuted n'
__device__ float g_pre1[SS*BB*GD];       // permuted n'
__device__ float g_dout[LMAXX*SS*BB*DHH];
__device__ float g_henc2[2][2*BB*HH];    // double-buffered encoder h
__device__ float g_cenc[2*BB*HH];
__device__ float g_hd  [BB*DHH];
__device__ float g_cd  [BB*DHH];
__device__ float g_ctx [BB*DHH];
__device__ float g_ghd [BB*GD];          // hd @ Wcat[:,512:]^T  (permuted n')
__device__ float g_Whhp[2*G4H*HH];       // permuted Whh rows [dir][1024][256]
__device__ float g_Wihp[2*G4H*EE];       // permuted Wih rows [dir][1024][512]
__device__ float g_bep [2*G4H];          // permuted encoder bias
__device__ float g_Wcat[GD*1024];        // permuted rows: [Wih_d[:, :512] | Whh_d]
__device__ float g_Wmid[GD*1024];        // permuted rows: Wih_d[:, 512:1536]
__device__ float g_Wprev[GD*512];        // permuted rows: Wih_d[:, 1536:2048]
__device__ float g_bdp [GD];             // permuted decoder bias
__device__ float g_ohcp[LMAXX*GD];       // permuted one-hot columns

__device__ unsigned g_barCount;
__device__ volatile unsigned g_barGen;

__device__ __forceinline__ float sigf(float x) { return 1.0f / (1.0f + __expf(-x)); }

// software grid barrier (all nb blocks co-resident)
__device__ __forceinline__ void gsync(unsigned nb) {
    __syncthreads();
    if (threadIdx.x == 0) {
        unsigned gen = g_barGen;
        __threadfence();
        if (atomicAdd(&g_barCount, 1) == nb - 1) {
            g_barCount = 0;
            __threadfence();
            g_barGen = gen + 1;
        } else {
            while (g_barGen == gen) {}
            __threadfence();
        }
    }
    __syncthreads();
}

// ---------------- prep: pack/permute weights, biases, zero states ----------------
#define PREP_TOTAL (163840 + 524288 + 1048576 + 2048 + 2097152 + 2097152 + 1048576 + 2048 + 8192)
__global__ void k_prep(const float* __restrict__ Whh_f, const float* __restrict__ Whh_b,
                       const float* __restrict__ Wih_f, const float* __restrict__ Wih_b,
                       const float* __restrict__ bih_f, const float* __restrict__ bhh_f,
                       const float* __restrict__ bih_b, const float* __restrict__ bhh_b,
                       const float* __restrict__ Wih_d, const float* __restrict__ Whh_d,
                       const float* __restrict__ bih_d, const float* __restrict__ bhh_d) {
    long long i = (long long)blockIdx.x * 256 + threadIdx.x;
    if (i < 163840) { // zero states
        if (i < 65536) g_henc2[i >> 15][i & 32767] = 0.f;
        else if (i < 98304) g_cenc[i - 65536] = 0.f;
        else if (i < 131072) g_hd[i - 98304] = 0.f;
        else g_cd[i - 131072] = 0.f;
        return;
    }
    i -= 163840;
    if (i < 524288) { // Whhp
        int dir = (int)(i >> 18), r = (int)(i & 262143);
        int np = r >> 8, k = r & 255;
        int n = enperm(np);
        g_Whhp[i] = (dir ? Whh_b : Whh_f)[n * HH + k];
        return;
    }
    i -= 524288;
    if (i < 1048576) { // Wihp
        int dir = (int)(i >> 19), r = (int)(i & 524287);
        int np = r >> 9, k = r & 511;
        int n = enperm(np);
        g_Wihp[i] = (dir ? Wih_b : Wih_f)[n * EE + k];
        return;
    }
    i -= 1048576;
    if (i < 2048) { // encoder bias
        int dir = (int)(i >> 10), np = (int)(i & 1023);
        int n = enperm(np);
        g_bep[i] = dir ? (bih_b[n] + bhh_b[n]) : (bih_f[n] + bhh_f[n]);
        return;
    }
    i -= 2048;
    if (i < 2097152) { // Wcat
        int np = (int)(i >> 10), k = (int)(i & 1023);
        int n = deperm(np);
        g_Wcat[i] = (k < 512) ? Wih_d[(size_t)n * LDWD + k] : Whh_d[(size_t)n * DHH + (k - 512)];
        return;
    }
    i -= 2097152;
    if (i < 2097152) { // Wmid
        int np = (int)(i >> 10), k = (int)(i & 1023);
        int n = deperm(np);
        g_Wmid[i] = Wih_d[(size_t)n * LDWD + 512 + k];
        return;
    }
    i -= 2097152;
    if (i < 1048576) { // Wprev
        int np = (int)(i >> 9), k = (int)(i & 511);
        int n = deperm(np);
        g_Wprev[i] = Wih_d[(size_t)n * LDWD + 1536 + k];
        return;
    }
    i -= 1048576;
    if (i < 2048) { // decoder bias
        int n = deperm((int)i);
        g_bdp[i] = bih_d[n] + bhh_d[n];
        return;
    }
    i -= 2048;
    if (i < 8192) { // one-hot columns
        int lvl = (int)(i >> 11), np = (int)(i & 2047);
        int n = deperm(np);
        g_ohcp[i] = Wih_d[(size_t)n * LDWD + GD + lvl];
        return;
    }
}

__global__ void k_embed(const int* __restrict__ seqs, const float* __restrict__ emb) {
    int m = blockIdx.x;            // m = s*64 + b
    int s0 = m >> 6, b = m & 63;
    int row = seqs[b * SS + s0];
    const float4* src = (const float4*)(emb + (size_t)row * EE);
    float4* dst = (float4*)(g_x + (size_t)m * EE);
    dst[threadIdx.x] = src[threadIdx.x];
}

// ---------------- conflict-free fp32 GEMM cores ----------------
// 64x64 tile: C = A[M,K] * W[N,K]^T. smem is k-major: lane-varying dim contiguous.
__device__ __forceinline__ void gemm64_core(float (*As)[68], float (*Ws)[68],
                                            const float* __restrict__ A, int lda,
                                            const float* __restrict__ A2,
                                            const float* __restrict__ W, int ldw,
                                            int K, int m0, int n0, float acc[4][4]) {
    int tid = threadIdx.x;
    int tm = (tid >> 4) << 2;
    int tn = (tid & 15) << 2;
    for (int k0 = 0; k0 < K; k0 += 16) {
        const float* Asrc = A;
        int kk0 = k0;
        if (A2 && k0 >= 512) { Asrc = A2; kk0 = k0 - 512; }
        #pragma unroll
        for (int i = tid; i < 1024; i += 256) {
            int r = i >> 4, k = i & 15;
            As[k][r] = Asrc[(size_t)(m0 + r) * lda + kk0 + k];
            Ws[k][r] = W[(size_t)(n0 + r) * ldw + k0 + k];
        }
        __syncthreads();
        #pragma unroll
        for (int k = 0; k < 16; k++) {
            float4 a4 = *(const float4*)&As[k][tm];
            float4 w4 = *(const float4*)&Ws[k][tn];
            acc[0][0] += a4.x * w4.x; acc[0][1] += a4.x * w4.y; acc[0][2] += a4.x * w4.z; acc[0][3] += a4.x * w4.w;
            acc[1][0] += a4.y * w4.x; acc[1][1] += a4.y * w4.y; acc[1][2] += a4.y * w4.z; acc[1][3] += a4.y * w4.w;
            acc[2][0] += a4.z * w4.x; acc[2][1] += a4.z * w4.y; acc[2][2] += a4.z * w4.z; acc[2][3] += a4.z * w4.w;
            acc[3][0] += a4.w * w4.x; acc[3][1] += a4.w * w4.y; acc[3][2] += a4.w * w4.z; acc[3][3] += a4.w * w4.w;
        }
        __syncthreads();
    }
}

// 16x64 tile: each thread owns 1 row x 4 cols
__device__ __forceinline__ void gemm16_core(float (*As2)[20], float (*Ws2)[68],
                                            const float* __restrict__ A, int lda,
                                            const float* __restrict__ W, int ldw,
                                            int K, int m0, int n0, float acc[4]) {
    int tid = threadIdx.x;
    int tr = tid >> 4;           // row 0..15
    int tn = (tid & 15) << 2;    // col*4
    for (int k0 = 0; k0 < K; k0 += 16) {
        As2[tid >> 4][tid & 15] = A[(size_t)(m0 + (tid >> 4)) * lda + k0 + (tid & 15)];
        #pragma unroll
        for (int i = tid; i < 1024; i += 256) {
            int r = i >> 4, k = i & 15;
            Ws2[k][r] = W[(size_t)(n0 + r) * ldw + k0 + k];
        }
        __syncthreads();
        #pragma unroll
        for (int kq = 0; kq < 16; kq += 4) {
            float4 a4 = *(const float4*)&As2[tr][kq];
            {
                float4 w4 = *(const float4*)&Ws2[kq + 0][tn];
                acc[0] += a4.x * w4.x; acc[1] += a4.x * w4.y; acc[2] += a4.x * w4.z; acc[3] += a4.x * w4.w;
            }
            {
                float4 w4 = *(const float4*)&Ws2[kq + 1][tn];
                acc[0] += a4.y * w4.x; acc[1] += a4.y * w4.y; acc[2] += a4.y * w4.z; acc[3] += a4.y * w4.w;
            }
            {
                float4 w4 = *(const float4*)&Ws2[kq + 2][tn];
                acc[0] += a4.z * w4.x; acc[1] += a4.z * w4.y; acc[2] += a4.z * w4.z; acc[3] += a4.z * w4.w;
            }
            {
                float4 w4 = *(const float4*)&Ws2[kq + 3][tn];
                acc[0] += a4.w * w4.x; acc[1] += a4.w * w4.y; acc[2] += a4.w * w4.z; acc[3] += a4.w * w4.w;
            }
        }
        __syncthreads();
    }
}

// generic big GEMM: C[M,N] = A*W^T (+add)(+bias). A2: second source for k>=512 (concat trick)
__global__ void __launch_bounds__(256) gemm_nt(const float* __restrict__ A, int lda,
                        const float* __restrict__ A2,
                        const float* __restrict__ W, int ldw,
                        float* __restrict__ C, int N, int K,
                        const float* __restrict__ add, const float* __restrict__ bias) {
    __shared__ __align__(16) float As[16][68];
    __shared__ __align__(16) float Ws[16][68];
    int m0 = blockIdx.x * 64, n0 = blockIdx.y * 64;
    float acc[4][4] = {};
    gemm64_core(As, Ws, A, lda, A2, W, ldw, K, m0, n0, acc);
    int tid = threadIdx.x;
    int tm = (tid >> 4) << 2, tn = (tid & 15) << 2;
    #pragma unroll
    for (int i = 0; i < 4; i++)
        #pragma unroll
        for (int j = 0; j < 4; j++) {
            size_t m = m0 + tm + i, n = n0 + tn + j;
            float v = acc[i][j];
            if (add)  v += add[m * N + n];
            if (bias) v += bias[n];
            C[m * N + n] = v;
        }
}

// ---------------- persistent encoder: fused gemm+cell, 1 barrier/step ----------------
__global__ void __launch_bounds__(256, 1) enc_persist() {
    __shared__ __align__(16) float As2[16][20];
    __shared__ __align__(16) float Ws2[16][68];
    __shared__ __align__(16) float gsm[16][68];
    int blk = blockIdx.x, tid = threadIdx.x;
    int dir = blk >> 6;
    int rem = blk & 63;
    int mi = rem >> 4;           // 0..3  (batch group of 16)
    int ni = rem & 15;           // 0..15 (n' tile of 64)
    int m0 = mi * 16, n0 = ni * 64;
    const float* W = g_Whhp + (size_t)dir * G4H * HH;
    int tr = tid >> 4, tnn = (tid & 15) << 2;
    int p = 0;
    for (int t = 0; t < SS; t++) {
        const float* A = g_henc2[p] + dir * BB * HH;
        const float* gx = dir ? (g_gxb + (size_t)(SS - 1 - t) * BB * G4H)
                              : (g_gxf + (size_t)t * BB * G4H);
        float acc[4] = {0.f, 0.f, 0.f, 0.f};
        gemm16_core(As2, Ws2, A, HH, W, HH, HH, m0, n0, acc);
        int b = m0 + tr;
        #pragma unroll
        for (int j = 0; j < 4; j++)
            gsm[tr][tnn + j] = acc[j] + gx[(size_t)b * G4H + n0 + tnn + j];
        __syncthreads();
        // cell: 16 b x 16 j
        {
            int bl = tid >> 4, jj = tid & 15;
            float gi = gsm[bl][jj], gf = gsm[bl][16 + jj], gg = gsm[bl][32 + jj], go = gsm[bl][48 + jj];
            int bb = m0 + bl, j = ni * 16 + jj;
            int ci = dir * BB * HH + bb * HH + j;
            float c = g_cenc[ci];
            c = sigf(gf) * c + sigf(gi) * tanhf(gg);
            float hn = sigf(go) * tanhf(c);
            g_cenc[ci] = c;
            g_henc2[p ^ 1][ci] = hn;
            int s0 = dir ? (SS - 1 - t) : t;
            g_h[((size_t)s0 * BB + bb) * DHH + dir * HH + j] = hn;
        }
        p ^= 1;
        gsync(NBE);
    }
}

// ---------------- persistent decoder: 2 barriers/step, fused cell ----------------
__global__ void __launch_bounds__(256, 1) dec_persist(int l0, int l1) {
    __shared__ __align__(16) float As2[16][20];
    __shared__ __align__(16) float Ws2[16][68];
    __shared__ __align__(16) float gsm[16][68];
    __shared__ __align__(16) float hd_s[DHH];
    __shared__ float sc[SS];
    __shared__ float red[128];
    int blk = blockIdx.x, tid = threadIdx.x;
    int tr = tid >> 4, tnn = (tid & 15) << 2;
    int bmi = blk >> 5, bni = blk & 31;      // phase-B tile
    for (int lvl = l0; lvl < l1; lvl++) {
        const float* pre = (lvl == 0) ? g_pre0 : g_pre1;
        const float* ohc = g_ohcp + lvl * GD;
        for (int t = 0; t < SS; t++) {
            // ===== phase A =====
            if (blk < 64) {
                // attention for batch b = blk
                int b = blk;
                for (int i = tid; i < DHH; i += 256) hd_s[i] = g_hd[b * DHH + i];
                __syncthreads();
                int warp = tid >> 5, lane = tid & 31;
                for (int s0 = warp; s0 < SS; s0 += 8) {
                    const float4* w4 = (const float4*)(g_wh + ((size_t)s0 * BB + b) * DHH);
                    const float4* h4 = (const float4*)hd_s;
                    float sum = 0.f;
                    #pragma unroll
                    for (int q = 0; q < 4; q++) {
                        float4 a = w4[lane * 4 + q];
                        float4 c = h4[lane * 4 + q];
                        sum += a.x * c.x + a.y * c.y + a.z * c.z + a.w * c.w;
                    }
                    #pragma unroll
                    for (int off = 16; off; off >>= 1) sum += __shfl_xor_sync(0xffffffffu, sum, off);
                    if (lane == 0) sc[s0] = sum;
                }
                __syncthreads();
                if (tid < 128) red[tid] = sc[tid];
                __syncthreads();
                for (int off = 64; off; off >>= 1) {
                    if (tid < off) red[tid] = fmaxf(red[tid], red[tid + off]);
                    __syncthreads();
                }
                float mx = red[0];
                __syncthreads();
                if (tid < 128) { float e = __expf(sc[tid] - mx); sc[tid] = e; red[tid] = e; }
                __syncthreads();
                for (int off = 64; off; off >>= 1) {
                    if (tid < off) red[tid] += red[tid + off];
                    __syncthreads();
                }
                float inv = 1.f / red[0];
                __syncthreads();
                for (int d = tid; d < DHH; d += 256) {
                    float acc = 0.f;
                    #pragma unroll 8
                    for (int s0 = 0; s0 < SS; s0++)
                        acc += sc[s0] * g_h[((size_t)s0 * BB + b) * DHH + d];
                    g_ctx[b * DHH + d] = acc * inv;
                }
            } else {
                // hd @ Wcat[:,512:]^T -> g_ghd, two 16x64 tiles per block
                int b2 = blk - 64;
                #pragma unroll
                for (int rep = 0; rep < 2; rep++) {
                    int tile = b2 * 2 + rep;
                    int mi = tile >> 5, ni = tile & 31;
                    float acc[4] = {0.f, 0.f, 0.f, 0.f};
                    gemm16_core(As2, Ws2, g_hd, DHH, g_Wcat + 512, 1024, DHH, mi * 16, ni * 64, acc);
                    int b = mi * 16 + tr;
                    #pragma unroll
                    for (int j = 0; j < 4; j++)
                        g_ghd[(size_t)b * GD + ni * 64 + tnn + j] = acc[j];
                    __syncthreads();
                }
            }
            gsync(NBD);
            // ===== phase B: ctx GEMM + cell, one 16x64 tile per block =====
            {
                float acc[4] = {0.f, 0.f, 0.f, 0.f};
                gemm16_core(As2, Ws2, g_ctx, DHH, g_Wcat, 1024, DHH, bmi * 16, bni * 64, acc);
                int b = bmi * 16 + tr;
                const float* prow = pre + ((size_t)t * BB + b) * GD;
                #pragma unroll
                for (int j = 0; j < 4; j++) {
                    int np = bni * 64 + tnn + j;
                    gsm[tr][tnn + j] = acc[j] + g_ghd[(size_t)b * GD + np] + prow[np] + ohc[np];
                }
                __syncthreads();
                int bl = tid >> 4, jj = tid & 15;
                float gi = gsm[bl][jj], gf = gsm[bl][16 + jj], gg = gsm[bl][32 + jj], go = gsm[bl][48 + jj];
                int bb = bmi * 16 + bl, j = bni * 16 + jj;
                int ci = bb * DHH + j;
                float c = g_cd[ci];
                c = sigf(gf) * c + sigf(gi) * tanhf(gg);
                float hn = sigf(go) * tanhf(c);
                g_cd[ci] = c;
                g_hd[ci] = hn;
                g_dout[(((size_t)lvl * SS + t) * BB + bb) * DHH + j] = hn;
            }
            gsync(NBD);
        }
    }
}

// ---------------- output projection ----------------
__global__ void out_proj(const float* __restrict__ W2, const float* __restrict__ b2,
                         float* __restrict__ out) {
    int m = blockIdx.x;
    int lane = threadIdx.x;
    const float* drow = g_dout + (size_t)m * DHH;
    float acc[CC] = {};
    for (int k = lane; k < DHH; k += 32) {
        float d = drow[k];
        #pragma unroll
        for (int c = 0; c < CC; c++) acc[c] += d * W2[c * DHH + k];
    }
    #pragma unroll
    for (int c = 0; c < CC; c++) {
        float v = acc[c];
        #pragma unroll
        for (int off = 16; off; off >>= 1) v += __shfl_xor_sync(0xffffffffu, v, off);
        if (lane == 0) out[(size_t)m * CC + c] = v + b2[c];
    }
}

// ---------------- host ----------------
static void* symaddr(const void* sym) { void* p = nullptr; cudaGetSymbolAddress(&p, sym); return p; }

extern "C" void kernel_launch(void* const* d_in, const int* in_sizes, int n_in,
                              void* d_out, int out_size) {
    const int*   seqs  = (const int*)d_in[0];
    const float* emb   = (const float*)d_in[2];
    const float* Wih_f = (const float*)d_in[3];
    const float* Whh_f = (const float*)d_in[4];
    const float* bih_f = (const float*)d_in[5];
    const float* bhh_f = (const float*)d_in[6];
    const float* Wih_b = (const float*)d_in[7];
    const float* Whh_b = (const float*)d_in[8];
    const float* bih_b = (const float*)d_in[9];
    const float* bhh_b = (const float*)d_in[10];
    const float* Wl    = (const float*)d_in[11];
    const float* Wih_d = (const float*)d_in[12];
    const float* Whh_d = (const float*)d_in[13];
    const float* bih_d = (const float*)d_in[14];
    const float* bhh_d = (const float*)d_in[15];
    const float* W2    = (const float*)d_in[16];
    const float* b2    = (const float*)d_in[17];
    float* out = (float*)d_out;

    float* px    = (float*)symaddr(g_x);
    float* pgxf  = (float*)symaddr(g_gxf);
    float* pgxb  = (float*)symaddr(g_gxb);
    float* ph    = (float*)symaddr(g_h);
    float* pwh   = (float*)symaddr(g_wh);
    float* ppreS = (float*)symaddr(g_preS);
    float* ppre0 = (float*)symaddr(g_pre0);
    float* ppre1 = (float*)symaddr(g_pre1);
    float* pdout = (float*)symaddr(g_dout);
    float* pWihp = (float*)symaddr(g_Wihp);
    float* pbep  = (float*)symaddr(g_bep);
    float* pWmid = (float*)symaddr(g_Wmid);
    float* pWprev= (float*)symaddr(g_Wprev);
    float* pbdp  = (float*)symaddr(g_bdp);

    // 0: prep (pack/permute/zero)
    k_prep<<<(PREP_TOTAL + 255) / 256, 256>>>(Whh_f, Whh_b, Wih_f, Wih_b,
                                              bih_f, bhh_f, bih_b, bhh_b,
                                              Wih_d, Whh_d, bih_d, bhh_d);
    // 1: embed
    k_embed<<<SS * BB, 128>>>(seqs, emb);
    // 2,3: encoder input GEMMs (permuted weights)
    gemm_nt<<<dim3(SS * BB / 64, G4H / 64), 256>>>(px, EE, nullptr, pWihp, EE, pgxf, G4H, EE, nullptr, pbep);
    gemm_nt<<<dim3(SS * BB / 64, G4H / 64), 256>>>(px, EE, nullptr, pWihp + G4H * EE, EE, pgxb, G4H, EE, nullptr, pbep + G4H);
    // 4: encoder recurrence
    enc_persist<<<NBE, 256>>>();
    // 5: preS = [h|x] @ Wmid^T + bd   (ncu -s 5 captures this)
    gemm_nt<<<dim3(SS * BB / 64, GD / 64), 256>>>(ph, DHH, px, pWmid, 1024, ppreS, GD, 1024, nullptr, pbdp);
    // 6: wh = h @ Wl^T
    gemm_nt<<<dim3(SS * BB / 64, DHH / 64), 256>>>(ph, DHH, nullptr, Wl, DHH, pwh, DHH, DHH, nullptr, nullptr);
    // 7: pre0 = preS + h @ Wprev^T
    gemm_nt<<<dim3(SS * BB / 64, GD / 64), 256>>>(ph, DHH, nullptr, pWprev, DHH, ppre0, GD, DHH, ppreS, nullptr);
    // 8: decoder level 0
    dec_persist<<<NBD, 256>>>(0, 1);
    // 9: pre1 = preS + dout0 @ Wprev^T
    gemm_nt<<<dim3(SS * BB / 64, GD / 64), 256>>>(pdout, DHH, nullptr, pWprev, DHH, ppre1, GD, DHH, ppreS, nullptr);
    // 10: decoder levels 1-3
    dec_persist<<<NBD, 256>>>(1, 4);
    // 11: logits
    out_proj<<<LMAXX * SS * BB, 32>>>(W2, b2, out);
}